// round 15
// baseline (speedup 1.0000x reference)
#include <cuda_runtime.h>
#include <cuda_fp16.h>
#include <math.h>
#include <cstdint>

#define NUM_ENVS 16384
#define NUM_AGENTS 16
#define IN_DIM 128
#define GCN_H 64
#define RNN_H 64
#define OUT_DIM 512
#define FLAT_H (NUM_AGENTS * RNN_H)      // 1024
#define NNODE ((size_t)NUM_ENVS * NUM_AGENTS)   // 262144

// ---------------- static device scratch -------------------------------------
__device__ float  g_hbuf[(size_t)NUM_ENVS * FLAT_H];
__device__ __align__(16) __half g_A2[NNODE * 128];        // [gcn | prev_h] fp16
__device__ __align__(16) __half g_A3[NNODE * RNN_H];      // h_new fp16
__device__ __align__(16) __half g_Wgt[GCN_H * IN_DIM];    // Wgcn^T fp16
__device__ __align__(16) __half g_B2[256 * 128];          // gate weights fp16
__device__ float g_b2[256];
__device__ __align__(16) __half g_B3[(size_t)OUT_DIM * FLAT_H];

// ---------------- helpers ---------------------------------------------------
__device__ __forceinline__ uint32_t smem_to_u32(const void* p) {
    uint32_t a;
    asm("{ .reg .u64 t; cvta.to.shared.u64 t, %1; cvt.u32.u64 %0, t; }" : "=r"(a) : "l"(p));
    return a;
}
// fast, saturation-safe activations (MUFU.EX2 path)
__device__ __forceinline__ float sig_fast(float v) {
    return __fdividef(1.0f, 1.0f + __expf(-v));          // v->+inf: 1, v->-inf: 0
}
__device__ __forceinline__ float tanh_fast(float v) {
    float e = __expf(2.0f * v);
    return 1.0f - __fdividef(2.0f, e + 1.0f);            // e->inf: 1, e->0: -1
}

__device__ __forceinline__ void ldmx4(uint32_t* r, uint32_t addr) {
    asm volatile("ldmatrix.sync.aligned.m8n8.x4.shared.b16 {%0,%1,%2,%3}, [%4];"
                 : "=r"(r[0]), "=r"(r[1]), "=r"(r[2]), "=r"(r[3]) : "r"(addr));
}
__device__ __forceinline__ void mma16816(float* d, const uint32_t* a, const uint32_t* b) {
    asm volatile("mma.sync.aligned.m16n8k16.row.col.f32.f16.f16.f32 "
                 "{%0,%1,%2,%3}, {%4,%5,%6,%7}, {%8,%9}, {%0,%1,%2,%3};"
                 : "+f"(d[0]), "+f"(d[1]), "+f"(d[2]), "+f"(d[3])
                 : "r"(a[0]), "r"(a[1]), "r"(a[2]), "r"(a[3]), "r"(b[0]), "r"(b[1]));
}
__device__ __forceinline__ void cp16(uint32_t dst, const void* src) {
    asm volatile("cp.async.cg.shared.global [%0], [%1], 16;" :: "r"(dst), "l"(src));
}
#define CP_COMMIT() asm volatile("cp.async.commit_group;")
#define CP_WAIT(N)  asm volatile("cp.async.wait_group %0;" :: "n"(N))

// ---------------------------------------------------------------------------
// pack weights (fp16)
// ---------------------------------------------------------------------------
#define PK_WGT (GCN_H * IN_DIM)
#define PK_B2  (256 * 128)
#define PK_WL  (OUT_DIM * FLAT_H)
#define PK_TOT (PK_WGT + PK_B2 + 256 + PK_WL)

__global__ void pack_w_kernel(const float* __restrict__ Wg,
                              const float* __restrict__ W_ih,
                              const float* __restrict__ W_hh,
                              const float* __restrict__ b_ih,
                              const float* __restrict__ b_hh,
                              const float* __restrict__ Wl) {
    int idx = blockIdx.x * 256 + threadIdx.x;
    if (idx < PK_WGT) {
        int n = idx >> 7, k = idx & 127;
        g_Wgt[idx] = __float2half_rn(Wg[k * GCN_H + n]);
    } else if (idx < PK_WGT + PK_B2) {
        int r = idx - PK_WGT;
        int n = r >> 7, k = r & 127;
        int j = n >> 2, g = n & 3;
        float w = 0.0f;
        if (g == 0)      w = (k < 64) ? W_ih[j * 64 + k]         : W_hh[j * 64 + (k - 64)];
        else if (g == 1) w = (k < 64) ? W_ih[(64 + j) * 64 + k]  : W_hh[(64 + j) * 64 + (k - 64)];
        else if (g == 2) w = (k < 64) ? W_ih[(128 + j) * 64 + k] : 0.0f;
        else             w = (k < 64) ? 0.0f                     : W_hh[(128 + j) * 64 + (k - 64)];
        g_B2[r] = __float2half_rn(w);
    } else if (idx < PK_WGT + PK_B2 + 256) {
        int n = idx - PK_WGT - PK_B2;
        int j = n >> 2, g = n & 3;
        float b;
        if (g == 0)      b = b_ih[j] + b_hh[j];
        else if (g == 1) b = b_ih[64 + j] + b_hh[64 + j];
        else if (g == 2) b = b_ih[128 + j];
        else             b = b_hh[128 + j];
        g_b2[n] = b;
    } else if (idx < PK_TOT) {
        int r = idx - PK_WGT - PK_B2 - 256;
        g_B3[r] = __float2half_rn(Wl[r]);
    }
}

// ---------------------------------------------------------------------------
// gcn_front (unchanged from R11, proven)
// ---------------------------------------------------------------------------
#define TS 40
#define F_SB4  0
#define F_SA   20480
#define F_XW   30720
#define F_ADJ  65536
#define F_DEG  73728
#define F_DNV  74240
#define F_SMEM 74752

__global__ __launch_bounds__(256, 2) void gcn_front(
    const float* __restrict__ x, const int* __restrict__ ei,
    const float* __restrict__ prev_h, const float* __restrict__ bg)
{
    extern __shared__ __align__(16) char smem[];
    __half* sA   = (__half*)(smem + F_SA);
    float*  xw_s = (float*)(smem + F_XW);
    float*  Adj  = (float*)(smem + F_ADJ);
    float*  deg  = (float*)(smem + F_DEG);
    float*  dnv  = (float*)(smem + F_DNV);

    const int t = threadIdx.x, wid = t >> 5, lane = t & 31;
    const size_t bm = (size_t)blockIdx.x * 128;
    const int e0 = blockIdx.x * 8;
    const int wm = (wid >> 1) * 32, wn = (wid & 1) * 32;
    const uint32_t sb = smem_to_u32(smem);
    const uint32_t ab = sb + F_SA;

    const int a_m = (lane & 7) + ((lane >> 3) & 1) * 8;
    const int a_k = ((lane >> 4) & 1) * 8;
    const int b_n = (lane & 7) + ((lane >> 4) & 1) * 8;
    const int b_k = ((lane >> 3) & 1) * 8;

    {
        int row = t >> 2, q = t & 3;
        #pragma unroll
        for (int c = 0; c < 4; c++)
            cp16(sb + F_SB4 + (uint32_t)c * 5120 + (uint32_t)(row * TS + q * 8) * 2,
                 g_Wgt + row * 128 + c * 32 + q * 8);
        CP_COMMIT();
    }

    #pragma unroll
    for (int i = 0; i < 8; i++) Adj[t + i * 256] = 0.0f;
    if (t < 128) deg[t] = 1.0f;

    float4 pax[4];
    auto lda = [&](int c) {
        #pragma unroll
        for (int i = 0; i < 4; i++) {
            int idx = t + i * 256;
            int row = idx >> 3, q = idx & 7;
            pax[i] = *(const float4*)(x + (bm + row) * IN_DIM + c * 32 + q * 4);
        }
    };
    auto stsa = [&]() {
        #pragma unroll
        for (int i = 0; i < 4; i++) {
            int idx = t + i * 256;
            int row = idx >> 3, q = idx & 7;
            __half2* ph = (__half2*)(sA + row * TS + q * 4);
            ph[0] = __floats2half2_rn(pax[i].x, pax[i].y);
            ph[1] = __floats2half2_rn(pax[i].z, pax[i].w);
        }
    };

    float acc[2][4][4];
    #pragma unroll
    for (int mt = 0; mt < 2; mt++)
        #pragma unroll
        for (int nt = 0; nt < 4; nt++)
            #pragma unroll
            for (int q = 0; q < 4; q++) acc[mt][nt][q] = 0.0f;

    lda(0);
    stsa();
    CP_WAIT(0);
    __syncthreads();

    for (int c = 0; c < 4; c++) {
        if (c < 3) lda(c + 1);

        const uint32_t bbc = sb + F_SB4 + (uint32_t)c * 5120;
        #pragma unroll
        for (int kk = 0; kk < 2; kk++) {
            uint32_t fA[2][4];
            #pragma unroll
            for (int mt = 0; mt < 2; mt++) {
                uint32_t off = (uint32_t)(((wm + mt * 16 + a_m) * TS + kk * 16 + a_k) * 2);
                ldmx4(fA[mt], ab + off);
            }
            #pragma unroll
            for (int ntg = 0; ntg < 2; ntg++) {
                uint32_t fB[4];
                uint32_t off = (uint32_t)(((wn + ntg * 16 + b_n) * TS + kk * 16 + b_k) * 2);
                ldmx4(fB, bbc + off);
                #pragma unroll
                for (int mt = 0; mt < 2; mt++)
                    #pragma unroll
                    for (int p = 0; p < 2; p++)
                        mma16816(acc[mt][ntg * 2 + p], fA[mt], &fB[p * 2]);
            }
        }
        __syncthreads();
        if (c < 3) {
            stsa();
            __syncthreads();
        }
    }

    const int fr = lane >> 2, fc = (lane & 3) * 2;
    #pragma unroll
    for (int mt = 0; mt < 2; mt++)
        #pragma unroll
        for (int nt = 0; nt < 4; nt++) {
            int col = wn + nt * 8 + fc;
            int r0 = wm + mt * 16 + fr;
            *(float2*)(xw_s + r0 * 68 + col)       = make_float2(acc[mt][nt][0], acc[mt][nt][1]);
            *(float2*)(xw_s + (r0 + 8) * 68 + col) = make_float2(acc[mt][nt][2], acc[mt][nt][3]);
        }

    int rr_[4], cc_[4];
    #pragma unroll
    for (int i = 0; i < 4; i++) {
        int eidx = t + i * 256;
        int el = eidx >> 7, e = eidx & 127;
        rr_[i] = ei[(size_t)(e0 + el) * 256 + e];
        cc_[i] = ei[(size_t)(e0 + el) * 256 + 128 + e];
    }
    __syncthreads();
    #pragma unroll
    for (int i = 0; i < 4; i++) {
        int el = (t + i * 256) >> 7;
        atomicAdd(&deg[el * 16 + cc_[i]], 1.0f);
    }
    __syncthreads();
    if (t < 128) dnv[t] = rsqrtf(deg[t]);
    __syncthreads();

    #pragma unroll
    for (int i = 0; i < 4; i++) {
        int el = (t + i * 256) >> 7;
        atomicAdd(&Adj[el * 256 + cc_[i] * 16 + rr_[i]],
                  dnv[el * 16 + rr_[i]] * dnv[el * 16 + cc_[i]]);
    }
    if (t < 128) {
        int el = t >> 4, r = t & 15;
        float d = dnv[t];
        atomicAdd(&Adj[el * 256 + r * 17], d * d);
    }
    __syncthreads();

    {
        const int j  = t & 63;
        const int cg = t >> 6;
        const float bgj = bg[j];
        #pragma unroll
        for (int el = 0; el < 8; el++) {
            float xv[NUM_AGENTS];
            #pragma unroll
            for (int r = 0; r < NUM_AGENTS; r++)
                xv[r] = xw_s[(el * 16 + r) * 68 + j];
            #pragma unroll
            for (int i = 0; i < 4; i++) {
                int c = cg * 4 + i;
                float s = 0.0f;
                const float* arow = Adj + el * 256 + c * 16;
                #pragma unroll
                for (int r = 0; r < NUM_AGENTS; r++) s += arow[r] * xv[r];
                s += bgj;
                size_t node = (size_t)(e0 + el) * 16 + c;
                g_A2[node * 128 + j] = __float2half_rn(s);
            }
        }
    }

    #pragma unroll
    for (int i = 0; i < 8; i++) {
        int idx = t + i * 256;
        int el = idx >> 8, f4 = idx & 255;
        float4 v = ((const float4*)(prev_h + (size_t)(e0 + el) * FLAT_H))[f4];
        int row = f4 >> 4, jj = (f4 & 15) * 4;
        size_t node = (size_t)(e0 + el) * 16 + row;
        __half2* ph = (__half2*)(g_A2 + node * 128 + 64 + jj);
        ph[0] = __floats2half2_rn(v.x, v.y);
        ph[1] = __floats2half2_rn(v.z, v.w);
    }
}

// ---------------------------------------------------------------------------
// GEMM2 (gates + GRU): persistent over M_ITERS m-tiles per CTA.
// BN=128 (N-split over 2 CTAs), BK=32, 256 thr, 2 CTAs/SM.
// B2 slice resident in smem (loaded once); A 3-buffer cp.async ring.
// ---------------------------------------------------------------------------
#define M_ITERS 4
#define G2_B0   0                            // B slice: 4 x 10240 = 40960
#define G2_A0   40960                        // A ring: 3 x 10240 = 30720
#define G2_HS   71680                        // float[128*36] = 18432
#define G2_B2S  90112                        // float[128]
#define G2_SMEM 90624

__global__ __launch_bounds__(256, 2) void gemm_gates(
    const float* __restrict__ prev_h,
    float* __restrict__ h_out)
{
    extern __shared__ __align__(16) char smem[];
    const uint32_t sb = smem_to_u32(smem);
    float* h_s  = (float*)(smem + G2_HS);     // stride 36
    float* b2_s = (float*)(smem + G2_B2S);

    const int t = threadIdx.x, wid = t >> 5, lane = t & 31;
    const int bn = blockIdx.x;                // 0..1 (j-half)
    const size_t tile0 = (size_t)blockIdx.y * M_ITERS;
    const int j0 = bn * 32;
    const int wm = (wid >> 2) * 64, wn = (wid & 3) * 32;

    const int a_m = (lane & 7) + ((lane >> 3) & 1) * 8;
    const int a_k = ((lane >> 4) & 1) * 8;
    const int b_n = (lane & 7) + ((lane >> 4) & 1) * 8;
    const int b_k = ((lane >> 3) & 1) * 8;

    // ---- load entire B2 slice once (group 0) ----
    {
        #pragma unroll
        for (int c = 0; c < 4; c++)
            #pragma unroll
            for (int i = 0; i < 2; i++) {
                int idx = t + i * 256;
                int row = idx >> 2, q = idx & 3;
                cp16(sb + G2_B0 + (uint32_t)c * 10240 + (uint32_t)(row * TS + q * 8) * 2,
                     g_B2 + (size_t)(bn * 128 + row) * 128 + c * 32 + q * 8);
            }
        CP_COMMIT();
    }

    // A chunk issue: global chunk g (tile g>>2, k-chunk g&3), ring slot g%3
    auto issueA = [&](int g) {
        int mt_ = g >> 2, cc = g & 3;
        size_t bm = (tile0 + mt_) * 128;
        uint32_t base = sb + G2_A0 + (uint32_t)(g % 3) * 10240;
        #pragma unroll
        for (int i = 0; i < 2; i++) {
            int idx = t + i * 256;
            int row = idx >> 2, q = idx & 3;
            cp16(base + (uint32_t)(row * TS + q * 8) * 2,
                 g_A2 + (bm + row) * 128 + cc * 32 + q * 8);
        }
        CP_COMMIT();
    };

    issueA(0);
    issueA(1);
    if (t < 128) b2_s[t] = g_b2[bn * 128 + t];

    const int NG = M_ITERS * 4;               // 16 global chunks
    const int fr = lane >> 2, fc = (lane & 3) * 2;

    for (int m = 0; m < M_ITERS; m++) {
        const size_t bm = (tile0 + m) * 128;

        // preload prev_h slice for this tile (consumed at epilogue; the
        // chunk-loop __syncthreads make it visible)
        #pragma unroll
        for (int i = 0; i < 4; i++) {
            int idx = t + i * 256;
            int row = idx >> 3, q = idx & 7;
            float4 v = *(const float4*)(prev_h + (bm + row) * RNN_H + j0 + q * 4);
            *(float4*)(h_s + row * 36 + q * 4) = v;
        }

        float acc[4][4][4];
        #pragma unroll
        for (int mt = 0; mt < 4; mt++)
            #pragma unroll
            for (int ns = 0; ns < 4; ns++)
                #pragma unroll
                for (int q = 0; q < 4; q++) acc[mt][ns][q] = 0.0f;

        for (int cl = 0; cl < 4; cl++) {
            const int g = m * 4 + cl;
            if (g < NG - 1) { CP_WAIT(1); } else { CP_WAIT(0); }
            __syncthreads();

            const uint32_t abase = sb + G2_A0 + (uint32_t)(g % 3) * 10240;
            const uint32_t bbase = sb + G2_B0 + (uint32_t)cl * 10240;
            #pragma unroll
            for (int kk = 0; kk < 2; kk++) {
                uint32_t fA[4][4];
                #pragma unroll
                for (int mt = 0; mt < 4; mt++) {
                    uint32_t off = (uint32_t)(((wm + mt * 16 + a_m) * TS + kk * 16 + a_k) * 2);
                    ldmx4(fA[mt], abase + off);
                }
                uint32_t fB[2][4];
                #pragma unroll
                for (int nt = 0; nt < 2; nt++) {
                    uint32_t off = (uint32_t)(((wn + nt * 16 + b_n) * TS + kk * 16 + b_k) * 2);
                    ldmx4(fB[nt], bbase + off);
                }
                #pragma unroll
                for (int mt = 0; mt < 4; mt++)
                    #pragma unroll
                    for (int ns = 0; ns < 4; ns++)
                        mma16816(acc[mt][ns], fA[mt], &fB[ns >> 1][(ns & 1) * 2]);
            }
            if (g + 2 < NG) issueA(g + 2);
        }

        // ---- fused GRU elementwise (fast activations) ----
        #pragma unroll
        for (int mt = 0; mt < 4; mt++) {
            #pragma unroll
            for (int ns = 0; ns < 4; ns++) {
                int n = wn + ns * 8 + fc;
                float v0 = acc[mt][ns][0] + b2_s[n];
                float v1 = acc[mt][ns][1] + b2_s[n + 1];
                float v2 = acc[mt][ns][2] + b2_s[n];
                float v3 = acc[mt][ns][3] + b2_s[n + 1];
                float p0 = __shfl_xor_sync(0xFFFFFFFF, v0, 1);
                float p1 = __shfl_xor_sync(0xFFFFFFFF, v1, 1);
                float p2 = __shfl_xor_sync(0xFFFFFFFF, v2, 1);
                float p3 = __shfl_xor_sync(0xFFFFFFFF, v3, 1);
                int jl = n >> 2;
                bool is01 = ((n & 2) == 0);
                float rs, zs, nxs, nhs;
                int mrow;
                if (is01) { rs = v0; zs = v1; nxs = p0; nhs = p1; mrow = wm + mt * 16 + fr; }
                else      { rs = p2; zs = p3; nxs = v2; nhs = v3; mrow = wm + mt * 16 + fr + 8; }
                float r = sig_fast(rs), z = sig_fast(zs);
                float nn = tanh_fast(nxs + r * nhs);
                float hp = h_s[mrow * 36 + jl];
                h_s[mrow * 36 + jl] = (1.0f - z) * nn + z * hp;
            }
        }
        __syncthreads();

        // ---- writeout: h fp32 slice + fp16 slice ----
        #pragma unroll
        for (int i = 0; i < 4; i++) {
            int idx = t + i * 256;
            int row = idx >> 3, q = idx & 7;
            float4 v = *(const float4*)(h_s + row * 36 + q * 4);
            *(float4*)(h_out + (bm + row) * RNN_H + j0 + q * 4) = v;
        }
        #pragma unroll
        for (int i = 0; i < 2; i++) {
            int idx = t + i * 256;
            int row = idx >> 2, q = idx & 3;
            const float* hp = h_s + row * 36 + q * 8;
            __half hv[8];
            #pragma unroll
            for (int e = 0; e < 8; e++) hv[e] = __float2half_rn(hp[e]);
            *(uint4*)(g_A3 + (bm + row) * RNN_H + j0 + q * 8) = *(uint4*)hv;
        }
        __syncthreads();   // protect h_s before next tile's preload
    }
}

// ---------------------------------------------------------------------------
// GEMM3 — fp16, 3-stage cp.async, 2 CTAs/SM.
// ---------------------------------------------------------------------------
#define G3_A   0
#define G3_B   10240
#define G3_STG 20480
#define G3_SMEM (3 * G3_STG)
#define NCHUNK (FLAT_H / 32)

__global__ __launch_bounds__(256, 2) void gemm_mma(
    const float* __restrict__ bias, float* __restrict__ C)
{
    extern __shared__ __align__(16) char smem[];
    const uint32_t sb = smem_to_u32(smem);

    const int t = threadIdx.x, wid = t >> 5, lane = t & 31;
    const int bn = blockIdx.x * 128, bm = blockIdx.y * 128;
    const int wm = (wid >> 2) * 64, wn = (wid & 3) * 32;

    const int a_m = (lane & 7) + ((lane >> 3) & 1) * 8;
    const int a_k = ((lane >> 4) & 1) * 8;
    const int b_n = (lane & 7) + ((lane >> 4) & 1) * 8;
    const int b_k = ((lane >> 3) & 1) * 8;

    auto issue = [&](int c, int s) {
        uint32_t base = sb + s * G3_STG;
        #pragma unroll
        for (int i = 0; i < 2; i++) {
            int idx = t + i * 256;
            int row = idx >> 2, q = idx & 3;
            uint32_t so = (uint32_t)(row * TS + q * 8) * 2;
            cp16(base + G3_A + so, g_A3 + (size_t)(bm + row) * FLAT_H + c * 32 + q * 8);
            cp16(base + G3_B + so, g_B3 + (size_t)(bn + row) * FLAT_H + c * 32 + q * 8);
        }
    };

    float acc[4][4][4];
    #pragma unroll
    for (int mt = 0; mt < 4; mt++)
        #pragma unroll
        for (int ns = 0; ns < 4; ns++)
            #pragma unroll
            for (int q = 0; q < 4; q++) acc[mt][ns][q] = 0.0f;

    issue(0, 0); CP_COMMIT();
    issue(1, 1); CP_COMMIT();

    for (int c = 0; c < NCHUNK; c++) {
        if (c < NCHUNK - 1) { CP_WAIT(1); } else { CP_WAIT(0); }
        __syncthreads();

        const uint32_t base = sb + (c % 3) * G3_STG;
        #pragma unroll
        for (int kk = 0; kk < 2; kk++) {
            const int akcol = kk * 16 + a_k;
            const int bkcol = kk * 16 + b_k;
            uint32_t fA[4][4];
            #pragma unroll
            for (int mt = 0; mt < 4; mt++) {
                uint32_t off = (uint32_t)(((wm + mt * 16 + a_m) * TS + akcol) * 2);
                ldmx4(fA[mt], base + G3_A + off);
            }
            uint32_t fB[2][4];
            #pragma unroll
            for (int nt = 0; nt < 2; nt++) {
                uint32_t off = (uint32_t)(((wn + nt * 16 + b_n) * TS + bkcol) * 2);
                ldmx4(fB[nt], base + G3_B + off);
            }
            #pragma unroll
            for (int mt = 0; mt < 4; mt++)
                #pragma unroll
                for (int ns = 0; ns < 4; ns++)
                    mma16816(acc[mt][ns], fA[mt], &fB[ns >> 1][(ns & 1) * 2]);
        }
        if (c + 2 < NCHUNK) { issue(c + 2, (c + 2) % 3); CP_COMMIT(); }
    }

    const int fr = lane >> 2, fc = (lane & 3) * 2;
    #pragma unroll
    for (int mt = 0; mt < 4; mt++)
        #pragma unroll
        for (int ns = 0; ns < 4; ns++) {
            int col = bn + wn + ns * 8 + fc;
            float2 bv = *(const float2*)(bias + col);
            int r0 = bm + wm + mt * 16 + fr;
            *(float2*)(C + (size_t)r0 * OUT_DIM + col) =
                make_float2(acc[mt][ns][0] + bv.x, acc[mt][ns][1] + bv.y);
            *(float2*)(C + (size_t)(r0 + 8) * OUT_DIM + col) =
                make_float2(acc[mt][ns][2] + bv.x, acc[mt][ns][3] + bv.y);
        }
}

// ---------------------------------------------------------------------------
extern "C" void kernel_launch(void* const* d_in, const int* in_sizes, int n_in,
                              void* d_out, int out_size) {
    const float* x     = (const float*)d_in[0];
    const int*   ei    = (const int*)  d_in[1];
    const float* ph    = (const float*)d_in[2];
    const float* Wg    = (const float*)d_in[3];
    const float* bg    = (const float*)d_in[4];
    const float* W_ih  = (const float*)d_in[5];
    const float* W_hh  = (const float*)d_in[6];
    const float* b_ih  = (const float*)d_in[7];
    const float* b_hh  = (const float*)d_in[8];
    const float* W_lin = (const float*)d_in[9];
    const float* b_lin = (const float*)d_in[10];

    float* out = (float*)d_out;
    bool has_nh = (out_size >= NUM_ENVS * (OUT_DIM + FLAT_H));
    float* hdst;
    if (has_nh) {
        hdst = out + (size_t)NUM_ENVS * OUT_DIM;
    } else {
        cudaGetSymbolAddress((void**)&hdst, g_hbuf);
    }

    static bool init = false;
    if (!init) {
        cudaFuncSetAttribute(gcn_front, cudaFuncAttributeMaxDynamicSharedMemorySize,
                             F_SMEM);
        cudaFuncSetAttribute(gemm_gates, cudaFuncAttributeMaxDynamicSharedMemorySize,
                             G2_SMEM);
        cudaFuncSetAttribute(gemm_mma, cudaFuncAttributeMaxDynamicSharedMemorySize,
                             G3_SMEM);
        init = true;
    }

    pack_w_kernel<<<(PK_TOT + 255) / 256, 256>>>(Wg, W_ih, W_hh, b_ih, b_hh, W_lin);
    gcn_front<<<NNODE / 128, 256, F_SMEM>>>(x, ei, ph, bg);
    gemm_gates<<<dim3(2, NNODE / 128 / M_ITERS), 256, G2_SMEM>>>(ph, hdst);
    gemm_mma<<<dim3(OUT_DIM / 128, NUM_ENVS / 128), 256, G3_SMEM>>>(b_lin, out);
}

// round 16
// speedup vs baseline: 1.4823x; 1.4823x over previous
#include <cuda_runtime.h>
#include <cuda_fp16.h>
#include <math.h>
#include <cstdint>

#define NUM_ENVS 16384
#define NUM_AGENTS 16
#define IN_DIM 128
#define GCN_H 64
#define RNN_H 64
#define OUT_DIM 512
#define FLAT_H (NUM_AGENTS * RNN_H)      // 1024
#define NNODE ((size_t)NUM_ENVS * NUM_AGENTS)   // 262144

// ---------------- static device scratch -------------------------------------
__device__ float  g_hbuf[(size_t)NUM_ENVS * FLAT_H];
__device__ __align__(16) __half g_A2[NNODE * 128];        // [gcn | prev_h] fp16
__device__ __align__(16) __half g_A3[NNODE * RNN_H];      // h_new fp16
__device__ __align__(16) __half g_Wgt[GCN_H * IN_DIM];    // Wgcn^T fp16
__device__ __align__(16) __half g_B2[256 * 128];          // gate weights fp16
__device__ float g_b2[256];
__device__ __align__(16) __half g_B3[(size_t)OUT_DIM * FLAT_H];

// ---------------- helpers ---------------------------------------------------
__device__ __forceinline__ uint32_t smem_to_u32(const void* p) {
    uint32_t a;
    asm("{ .reg .u64 t; cvta.to.shared.u64 t, %1; cvt.u32.u64 %0, t; }" : "=r"(a) : "l"(p));
    return a;
}
__device__ __forceinline__ float sig_fast(float v) {
    return __fdividef(1.0f, 1.0f + __expf(-v));
}
__device__ __forceinline__ float tanh_fast(float v) {
    float e = __expf(2.0f * v);
    return 1.0f - __fdividef(2.0f, e + 1.0f);
}
__device__ __forceinline__ void ldmx4(uint32_t* r, uint32_t addr) {
    asm volatile("ldmatrix.sync.aligned.m8n8.x4.shared.b16 {%0,%1,%2,%3}, [%4];"
                 : "=r"(r[0]), "=r"(r[1]), "=r"(r[2]), "=r"(r[3]) : "r"(addr));
}
__device__ __forceinline__ void mma16816(float* d, const uint32_t* a, const uint32_t* b) {
    asm volatile("mma.sync.aligned.m16n8k16.row.col.f32.f16.f16.f32 "
                 "{%0,%1,%2,%3}, {%4,%5,%6,%7}, {%8,%9}, {%0,%1,%2,%3};"
                 : "+f"(d[0]), "+f"(d[1]), "+f"(d[2]), "+f"(d[3])
                 : "r"(a[0]), "r"(a[1]), "r"(a[2]), "r"(a[3]), "r"(b[0]), "r"(b[1]));
}
__device__ __forceinline__ void cp16(uint32_t dst, const void* src) {
    asm volatile("cp.async.cg.shared.global [%0], [%1], 16;" :: "r"(dst), "l"(src));
}
#define CP_COMMIT() asm volatile("cp.async.commit_group;")
#define CP_WAIT(N)  asm volatile("cp.async.wait_group %0;" :: "n"(N))

// ---------------------------------------------------------------------------
// pack weights (fp16)
// ---------------------------------------------------------------------------
#define PK_WGT (GCN_H * IN_DIM)
#define PK_B2  (256 * 128)
#define PK_WL  (OUT_DIM * FLAT_H)
#define PK_TOT (PK_WGT + PK_B2 + 256 + PK_WL)

__global__ void pack_w_kernel(const float* __restrict__ Wg,
                              const float* __restrict__ W_ih,
                              const float* __restrict__ W_hh,
                              const float* __restrict__ b_ih,
                              const float* __restrict__ b_hh,
                              const float* __restrict__ Wl) {
    int idx = blockIdx.x * 256 + threadIdx.x;
    if (idx < PK_WGT) {
        int n = idx >> 7, k = idx & 127;
        g_Wgt[idx] = __float2half_rn(Wg[k * GCN_H + n]);
    } else if (idx < PK_WGT + PK_B2) {
        int r = idx - PK_WGT;
        int n = r >> 7, k = r & 127;
        int j = n >> 2, g = n & 3;
        float w = 0.0f;
        if (g == 0)      w = (k < 64) ? W_ih[j * 64 + k]         : W_hh[j * 64 + (k - 64)];
        else if (g == 1) w = (k < 64) ? W_ih[(64 + j) * 64 + k]  : W_hh[(64 + j) * 64 + (k - 64)];
        else if (g == 2) w = (k < 64) ? W_ih[(128 + j) * 64 + k] : 0.0f;
        else             w = (k < 64) ? 0.0f                     : W_hh[(128 + j) * 64 + (k - 64)];
        g_B2[r] = __float2half_rn(w);
    } else if (idx < PK_WGT + PK_B2 + 256) {
        int n = idx - PK_WGT - PK_B2;
        int j = n >> 2, g = n & 3;
        float b;
        if (g == 0)      b = b_ih[j] + b_hh[j];
        else if (g == 1) b = b_ih[64 + j] + b_hh[64 + j];
        else if (g == 2) b = b_ih[128 + j];
        else             b = b_hh[128 + j];
        g_b2[n] = b;
    } else if (idx < PK_TOT) {
        int r = idx - PK_WGT - PK_B2 - 256;
        g_B3[r] = __float2half_rn(Wl[r]);
    }
}

// ---------------------------------------------------------------------------
// gcn_front: persistent over FR_ITERS tiles; double-buffered phase-1 A
// (R14 inner loop: 1 sync/chunk). 256 thr, 2 CTAs/SM.
// ---------------------------------------------------------------------------
#define TS 40
#define FR_ITERS 2
#define F_SB4  0                          // Wgt: 20480
#define F_SA   20480                      // A buf0: 10240
#define F_SA2  30720                      // A buf1: 10240
#define F_XW   40960                      // float[128*68] = 34816
#define F_ADJ  75776                      // float[8*256] = 8192
#define F_DEG  83968                      // 512
#define F_DNV  84480                      // 512
#define F_SMEM 84992

__global__ __launch_bounds__(256, 2) void gcn_front(
    const float* __restrict__ x, const int* __restrict__ ei,
    const float* __restrict__ prev_h, const float* __restrict__ bg)
{
    extern __shared__ __align__(16) char smem[];
    float*  xw_s = (float*)(smem + F_XW);
    float*  Adj  = (float*)(smem + F_ADJ);
    float*  deg  = (float*)(smem + F_DEG);
    float*  dnv  = (float*)(smem + F_DNV);

    const int t = threadIdx.x, wid = t >> 5, lane = t & 31;
    const int wm = (wid >> 1) * 32, wn = (wid & 1) * 32;
    const uint32_t sb = smem_to_u32(smem);
    const uint32_t abuf[2] = { sb + F_SA, sb + F_SA2 };

    const int a_m = (lane & 7) + ((lane >> 3) & 1) * 8;
    const int a_k = ((lane >> 4) & 1) * 8;
    const int b_n = (lane & 7) + ((lane >> 4) & 1) * 8;
    const int b_k = ((lane >> 3) & 1) * 8;
    const int fr = lane >> 2, fc = (lane & 3) * 2;

    // ---- Wgt loaded ONCE per CTA ----
    {
        int row = t >> 2, q = t & 3;
        #pragma unroll
        for (int c = 0; c < 4; c++)
            cp16(sb + F_SB4 + (uint32_t)c * 5120 + (uint32_t)(row * TS + q * 8) * 2,
                 g_Wgt + row * 128 + c * 32 + q * 8);
        CP_COMMIT();
    }

    for (int it = 0; it < FR_ITERS; it++) {
        const size_t tile = (size_t)blockIdx.x * FR_ITERS + it;
        const size_t bm = tile * 128;
        const int e0 = (int)tile * 8;

        // zero Adj/deg (prev tile finished via trailing sync)
        #pragma unroll
        for (int i = 0; i < 8; i++) Adj[t + i * 256] = 0.0f;
        if (t < 128) deg[t] = 1.0f;

        float4 pax[4];
        auto lda = [&](int c) {
            #pragma unroll
            for (int i = 0; i < 4; i++) {
                int idx = t + i * 256;
                int row = idx >> 3, q = idx & 7;
                pax[i] = *(const float4*)(x + (bm + row) * IN_DIM + c * 32 + q * 4);
            }
        };
        auto stsa = [&](int buf) {
            __half* sA1 = (__half*)(smem + (buf ? F_SA2 : F_SA));
            #pragma unroll
            for (int i = 0; i < 4; i++) {
                int idx = t + i * 256;
                int row = idx >> 3, q = idx & 7;
                __half2* ph = (__half2*)(sA1 + row * TS + q * 4);
                ph[0] = __floats2half2_rn(pax[i].x, pax[i].y);
                ph[1] = __floats2half2_rn(pax[i].z, pax[i].w);
            }
        };

        float acc[2][4][4];
        #pragma unroll
        for (int mt = 0; mt < 2; mt++)
            #pragma unroll
            for (int nt = 0; nt < 4; nt++)
                #pragma unroll
                for (int q = 0; q < 4; q++) acc[mt][nt][q] = 0.0f;

        lda(0);
        stsa(0);
        if (it == 0) CP_WAIT(0);          // Wgt resident
        __syncthreads();

        for (int c = 0; c < 4; c++) {
            if (c < 3) lda(c + 1);                 // LDG overlaps MMA

            const uint32_t ab = abuf[c & 1];
            const uint32_t bbc = sb + F_SB4 + (uint32_t)c * 5120;
            #pragma unroll
            for (int kk = 0; kk < 2; kk++) {
                uint32_t fA[2][4];
                #pragma unroll
                for (int mt = 0; mt < 2; mt++) {
                    uint32_t off = (uint32_t)(((wm + mt * 16 + a_m) * TS + kk * 16 + a_k) * 2);
                    ldmx4(fA[mt], ab + off);
                }
                #pragma unroll
                for (int ntg = 0; ntg < 2; ntg++) {
                    uint32_t fB[4];
                    uint32_t off = (uint32_t)(((wn + ntg * 16 + b_n) * TS + kk * 16 + b_k) * 2);
                    ldmx4(fB, bbc + off);
                    #pragma unroll
                    for (int mt = 0; mt < 2; mt++)
                        #pragma unroll
                        for (int p = 0; p < 2; p++)
                            mma16816(acc[mt][ntg * 2 + p], fA[mt], &fB[p * 2]);
                }
            }
            if (c < 3) stsa((c + 1) & 1);          // write idle buffer
            __syncthreads();                       // one sync per chunk
        }

        // ---- xw fragments -> smem ----
        #pragma unroll
        for (int mt = 0; mt < 2; mt++)
            #pragma unroll
            for (int nt = 0; nt < 4; nt++) {
                int col = wn + nt * 8 + fc;
                int r0 = wm + mt * 16 + fr;
                *(float2*)(xw_s + r0 * 68 + col)       = make_float2(acc[mt][nt][0], acc[mt][nt][1]);
                *(float2*)(xw_s + (r0 + 8) * 68 + col) = make_float2(acc[mt][nt][2], acc[mt][nt][3]);
            }

        // ---- edges: degree / adjacency ----
        int rr_[4], cc_[4];
        #pragma unroll
        for (int i = 0; i < 4; i++) {
            int eidx = t + i * 256;
            int el = eidx >> 7, e = eidx & 127;
            rr_[i] = ei[(size_t)(e0 + el) * 256 + e];
            cc_[i] = ei[(size_t)(e0 + el) * 256 + 128 + e];
        }
        __syncthreads();
        #pragma unroll
        for (int i = 0; i < 4; i++) {
            int el = (t + i * 256) >> 7;
            atomicAdd(&deg[el * 16 + cc_[i]], 1.0f);
        }
        __syncthreads();
        if (t < 128) dnv[t] = rsqrtf(deg[t]);
        __syncthreads();
        #pragma unroll
        for (int i = 0; i < 4; i++) {
            int el = (t + i * 256) >> 7;
            atomicAdd(&Adj[el * 256 + cc_[i] * 16 + rr_[i]],
                      dnv[el * 16 + rr_[i]] * dnv[el * 16 + cc_[i]]);
        }
        if (t < 128) {
            int el = t >> 4, r = t & 15;
            float d = dnv[t];
            atomicAdd(&Adj[el * 256 + r * 17], d * d);
        }
        __syncthreads();

        // ---- agg = Adj @ xw + bias -> g_A2 cols [0,64) ----
        {
            const int j  = t & 63;
            const int cg = t >> 6;
            const float bgj = bg[j];
            #pragma unroll
            for (int el = 0; el < 8; el++) {
                float xv[NUM_AGENTS];
                #pragma unroll
                for (int r = 0; r < NUM_AGENTS; r++)
                    xv[r] = xw_s[(el * 16 + r) * 68 + j];
                #pragma unroll
                for (int i = 0; i < 4; i++) {
                    int c = cg * 4 + i;
                    float s = 0.0f;
                    const float* arow = Adj + el * 256 + c * 16;
                    #pragma unroll
                    for (int r = 0; r < NUM_AGENTS; r++) s += arow[r] * xv[r];
                    s += bgj;
                    size_t node = (size_t)(e0 + el) * 16 + c;
                    g_A2[node * 128 + j] = __float2half_rn(s);
                }
            }
        }

        // ---- prev_h -> g_A2 cols [64,128) ----
        #pragma unroll
        for (int i = 0; i < 8; i++) {
            int idx = t + i * 256;
            int el = idx >> 8, f4 = idx & 255;
            float4 v = ((const float4*)(prev_h + (size_t)(e0 + el) * FLAT_H))[f4];
            int row = f4 >> 4, jj = (f4 & 15) * 4;
            size_t node = (size_t)(e0 + el) * 16 + row;
            __half2* ph = (__half2*)(g_A2 + node * 128 + 64 + jj);
            ph[0] = __floats2half2_rn(v.x, v.y);
            ph[1] = __floats2half2_rn(v.z, v.w);
        }
        __syncthreads();   // protect Adj/xw/sA before next tile
    }
}

// ---------------------------------------------------------------------------
// GEMM2 (gates + GRU): persistent over M_ITERS m-tiles per CTA (R12, proven).
// ---------------------------------------------------------------------------
#define M_ITERS 4
#define G2_B0   0                            // B slice: 4 x 10240 = 40960
#define G2_A0   40960                        // A ring: 3 x 10240 = 30720
#define G2_HS   71680                        // float[128*36] = 18432
#define G2_B2S  90112                        // float[128]
#define G2_SMEM 90624

__global__ __launch_bounds__(256, 2) void gemm_gates(
    const float* __restrict__ prev_h,
    float* __restrict__ h_out)
{
    extern __shared__ __align__(16) char smem[];
    const uint32_t sb = smem_to_u32(smem);
    float* h_s  = (float*)(smem + G2_HS);     // stride 36
    float* b2_s = (float*)(smem + G2_B2S);

    const int t = threadIdx.x, wid = t >> 5, lane = t & 31;
    const int bn = blockIdx.x;                // 0..1 (j-half)
    const size_t tile0 = (size_t)blockIdx.y * M_ITERS;
    const int j0 = bn * 32;
    const int wm = (wid >> 2) * 64, wn = (wid & 3) * 32;

    const int a_m = (lane & 7) + ((lane >> 3) & 1) * 8;
    const int a_k = ((lane >> 4) & 1) * 8;
    const int b_n = (lane & 7) + ((lane >> 4) & 1) * 8;
    const int b_k = ((lane >> 3) & 1) * 8;

    {
        #pragma unroll
        for (int c = 0; c < 4; c++)
            #pragma unroll
            for (int i = 0; i < 2; i++) {
                int idx = t + i * 256;
                int row = idx >> 2, q = idx & 3;
                cp16(sb + G2_B0 + (uint32_t)c * 10240 + (uint32_t)(row * TS + q * 8) * 2,
                     g_B2 + (size_t)(bn * 128 + row) * 128 + c * 32 + q * 8);
            }
        CP_COMMIT();
    }

    auto issueA = [&](int g) {
        int mt_ = g >> 2, cc = g & 3;
        size_t bm = (tile0 + mt_) * 128;
        uint32_t base = sb + G2_A0 + (uint32_t)(g % 3) * 10240;
        #pragma unroll
        for (int i = 0; i < 2; i++) {
            int idx = t + i * 256;
            int row = idx >> 2, q = idx & 3;
            cp16(base + (uint32_t)(row * TS + q * 8) * 2,
                 g_A2 + (bm + row) * 128 + cc * 32 + q * 8);
        }
        CP_COMMIT();
    };

    issueA(0);
    issueA(1);
    if (t < 128) b2_s[t] = g_b2[bn * 128 + t];

    const int NG = M_ITERS * 4;
    const int fr = lane >> 2, fc = (lane & 3) * 2;

    for (int m = 0; m < M_ITERS; m++) {
        const size_t bm = (tile0 + m) * 128;

        #pragma unroll
        for (int i = 0; i < 4; i++) {
            int idx = t + i * 256;
            int row = idx >> 3, q = idx & 7;
            float4 v = *(const float4*)(prev_h + (bm + row) * RNN_H + j0 + q * 4);
            *(float4*)(h_s + row * 36 + q * 4) = v;
        }

        float acc[4][4][4];
        #pragma unroll
        for (int mt = 0; mt < 4; mt++)
            #pragma unroll
            for (int ns = 0; ns < 4; ns++)
                #pragma unroll
                for (int q = 0; q < 4; q++) acc[mt][ns][q] = 0.0f;

        for (int cl = 0; cl < 4; cl++) {
            const int g = m * 4 + cl;
            if (g < NG - 1) { CP_WAIT(1); } else { CP_WAIT(0); }
            __syncthreads();

            const uint32_t abase = sb + G2_A0 + (uint32_t)(g % 3) * 10240;
            const uint32_t bbase = sb + G2_B0 + (uint32_t)cl * 10240;
            #pragma unroll
            for (int kk = 0; kk < 2; kk++) {
                uint32_t fA[4][4];
                #pragma unroll
                for (int mt = 0; mt < 4; mt++) {
                    uint32_t off = (uint32_t)(((wm + mt * 16 + a_m) * TS + kk * 16 + a_k) * 2);
                    ldmx4(fA[mt], abase + off);
                }
                uint32_t fB[2][4];
                #pragma unroll
                for (int nt = 0; nt < 2; nt++) {
                    uint32_t off = (uint32_t)(((wn + nt * 16 + b_n) * TS + kk * 16 + b_k) * 2);
                    ldmx4(fB[nt], bbase + off);
                }
                #pragma unroll
                for (int mt = 0; mt < 4; mt++)
                    #pragma unroll
                    for (int ns = 0; ns < 4; ns++)
                        mma16816(acc[mt][ns], fA[mt], &fB[ns >> 1][(ns & 1) * 2]);
            }
            if (g + 2 < NG) issueA(g + 2);
        }

        // ---- fused GRU elementwise (fast activations) ----
        #pragma unroll
        for (int mt = 0; mt < 4; mt++) {
            #pragma unroll
            for (int ns = 0; ns < 4; ns++) {
                int n = wn + ns * 8 + fc;
                float v0 = acc[mt][ns][0] + b2_s[n];
                float v1 = acc[mt][ns][1] + b2_s[n + 1];
                float v2 = acc[mt][ns][2] + b2_s[n];
                float v3 = acc[mt][ns][3] + b2_s[n + 1];
                float p0 = __shfl_xor_sync(0xFFFFFFFF, v0, 1);
                float p1 = __shfl_xor_sync(0xFFFFFFFF, v1, 1);
                float p2 = __shfl_xor_sync(0xFFFFFFFF, v2, 1);
                float p3 = __shfl_xor_sync(0xFFFFFFFF, v3, 1);
                int jl = n >> 2;
                bool is01 = ((n & 2) == 0);
                float rs, zs, nxs, nhs;
                int mrow;
                if (is01) { rs = v0; zs = v1; nxs = p0; nhs = p1; mrow = wm + mt * 16 + fr; }
                else      { rs = p2; zs = p3; nxs = v2; nhs = v3; mrow = wm + mt * 16 + fr + 8; }
                float r = sig_fast(rs), z = sig_fast(zs);
                float nn = tanh_fast(nxs + r * nhs);
                float hp = h_s[mrow * 36 + jl];
                h_s[mrow * 36 + jl] = (1.0f - z) * nn + z * hp;
            }
        }
        __syncthreads();

        // ---- writeout: h fp32 slice + fp16 slice ----
        #pragma unroll
        for (int i = 0; i < 4; i++) {
            int idx = t + i * 256;
            int row = idx >> 3, q = idx & 7;
            float4 v = *(const float4*)(h_s + row * 36 + q * 4);
            *(float4*)(h_out + (bm + row) * RNN_H + j0 + q * 4) = v;
        }
        #pragma unroll
        for (int i = 0; i < 2; i++) {
            int idx = t + i * 256;
            int row = idx >> 2, q = idx & 3;
            const float* hp = h_s + row * 36 + q * 8;
            __half hv[8];
            #pragma unroll
            for (int e = 0; e < 8; e++) hv[e] = __float2half_rn(hp[e]);
            *(uint4*)(g_A3 + (bm + row) * RNN_H + j0 + q * 8) = *(uint4*)hv;
        }
        __syncthreads();
    }
}

// ---------------------------------------------------------------------------
// GEMM3 — fp16, 3-stage cp.async, 2 CTAs/SM (proven).
// ---------------------------------------------------------------------------
#define G3_A   0
#define G3_B   10240
#define G3_STG 20480
#define G3_SMEM (3 * G3_STG)
#define NCHUNK (FLAT_H / 32)

__global__ __launch_bounds__(256, 2) void gemm_mma(
    const float* __restrict__ bias, float* __restrict__ C)
{
    extern __shared__ __align__(16) char smem[];
    const uint32_t sb = smem_to_u32(smem);

    const int t = threadIdx.x, wid = t >> 5, lane = t & 31;
    const int bn = blockIdx.x * 128, bm = blockIdx.y * 128;
    const int wm = (wid >> 2) * 64, wn = (wid & 3) * 32;

    const int a_m = (lane & 7) + ((lane >> 3) & 1) * 8;
    const int a_k = ((lane >> 4) & 1) * 8;
    const int b_n = (lane & 7) + ((lane >> 4) & 1) * 8;
    const int b_k = ((lane >> 3) & 1) * 8;

    auto issue = [&](int c, int s) {
        uint32_t base = sb + s * G3_STG;
        #pragma unroll
        for (int i = 0; i < 2; i++) {
            int idx = t + i * 256;
            int row = idx >> 2, q = idx & 3;
            uint32_t so = (uint32_t)(row * TS + q * 8) * 2;
            cp16(base + G3_A + so, g_A3 + (size_t)(bm + row) * FLAT_H + c * 32 + q * 8);
            cp16(base + G3_B + so, g_B3 + (size_t)(bn + row) * FLAT_H + c * 32 + q * 8);
        }
    };

    float acc[4][4][4];
    #pragma unroll
    for (int mt = 0; mt < 4; mt++)
        #pragma unroll
        for (int ns = 0; ns < 4; ns++)
            #pragma unroll
            for (int q = 0; q < 4; q++) acc[mt][ns][q] = 0.0f;

    issue(0, 0); CP_COMMIT();
    issue(1, 1); CP_COMMIT();

    for (int c = 0; c < NCHUNK; c++) {
        if (c < NCHUNK - 1) { CP_WAIT(1); } else { CP_WAIT(0); }
        __syncthreads();

        const uint32_t base = sb + (c % 3) * G3_STG;
        #pragma unroll
        for (int kk = 0; kk < 2; kk++) {
            const int akcol = kk * 16 + a_k;
            const int bkcol = kk * 16 + b_k;
            uint32_t fA[4][4];
            #pragma unroll
            for (int mt = 0; mt < 4; mt++) {
                uint32_t off = (uint32_t)(((wm + mt * 16 + a_m) * TS + akcol) * 2);
                ldmx4(fA[mt], base + G3_A + off);
            }
            uint32_t fB[2][4];
            #pragma unroll
            for (int nt = 0; nt < 2; nt++) {
                uint32_t off = (uint32_t)(((wn + nt * 16 + b_n) * TS + bkcol) * 2);
                ldmx4(fB[nt], base + G3_B + off);
            }
            #pragma unroll
            for (int mt = 0; mt < 4; mt++)
                #pragma unroll
                for (int ns = 0; ns < 4; ns++)
                    mma16816(acc[mt][ns], fA[mt], &fB[ns >> 1][(ns & 1) * 2]);
        }
        if (c + 2 < NCHUNK) { issue(c + 2, (c + 2) % 3); CP_COMMIT(); }
    }

    const int fr = lane >> 2, fc = (lane & 3) * 2;
    #pragma unroll
    for (int mt = 0; mt < 4; mt++)
        #pragma unroll
        for (int ns = 0; ns < 4; ns++) {
            int col = bn + wn + ns * 8 + fc;
            float2 bv = *(const float2*)(bias + col);
            int r0 = bm + wm + mt * 16 + fr;
            *(float2*)(C + (size_t)r0 * OUT_DIM + col) =
                make_float2(acc[mt][ns][0] + bv.x, acc[mt][ns][1] + bv.y);
            *(float2*)(C + (size_t)(r0 + 8) * OUT_DIM + col) =
                make_float2(acc[mt][ns][2] + bv.x, acc[mt][ns][3] + bv.y);
        }
}

// ---------------------------------------------------------------------------
extern "C" void kernel_launch(void* const* d_in, const int* in_sizes, int n_in,
                              void* d_out, int out_size) {
    const float* x     = (const float*)d_in[0];
    const int*   ei    = (const int*)  d_in[1];
    const float* ph    = (const float*)d_in[2];
    const float* Wg    = (const float*)d_in[3];
    const float* bg    = (const float*)d_in[4];
    const float* W_ih  = (const float*)d_in[5];
    const float* W_hh  = (const float*)d_in[6];
    const float* b_ih  = (const float*)d_in[7];
    const float* b_hh  = (const float*)d_in[8];
    const float* W_lin = (const float*)d_in[9];
    const float* b_lin = (const float*)d_in[10];

    float* out = (float*)d_out;
    bool has_nh = (out_size >= NUM_ENVS * (OUT_DIM + FLAT_H));
    float* hdst;
    if (has_nh) {
        hdst = out + (size_t)NUM_ENVS * OUT_DIM;
    } else {
        cudaGetSymbolAddress((void**)&hdst, g_hbuf);
    }

    static bool init = false;
    if (!init) {
        cudaFuncSetAttribute(gcn_front, cudaFuncAttributeMaxDynamicSharedMemorySize,
                             F_SMEM);
        cudaFuncSetAttribute(gemm_gates, cudaFuncAttributeMaxDynamicSharedMemorySize,
                             G2_SMEM);
        cudaFuncSetAttribute(gemm_mma, cudaFuncAttributeMaxDynamicSharedMemorySize,
                             G3_SMEM);
        init = true;
    }

    pack_w_kernel<<<(PK_TOT + 255) / 256, 256>>>(Wg, W_ih, W_hh, b_ih, b_hh, W_lin);
    gcn_front<<<NNODE / 128 / FR_ITERS, 256, F_SMEM>>>(x, ei, ph, bg);
    gemm_gates<<<dim3(2, NNODE / 128 / M_ITERS), 256, G2_SMEM>>>(ph, hdst);
    gemm_mma<<<dim3(OUT_DIM / 128, NUM_ENVS / 128), 256, G3_SMEM>>>(b_lin, out);
}